// round 2
// baseline (speedup 1.0000x reference)
#include <cuda_runtime.h>
#include <cuda_fp16.h>
#include <math.h>
#include <stdint.h>

// ---------------------------------------------------------------------------
// DecoderRNN: 240-step LSTM decoder, B=512, H=2048, OUT=165, NCLS=40
// Persistent-kernel version: ONE grid-resident kernel runs all 240 steps with
// software grid barriers, so the CUDA graph has ~8 nodes (fixes the 2MB
// graph-upload teardown violation from the 966-node version).
// ---------------------------------------------------------------------------

#define BATCH   512
#define HID     2048
#define G4      8192        // 4*HID
#define OUTD    165
#define NCLS    40
#define SEQL    240
#define WIH_COLS 330        // 2*OUTD
#define KXP     2240        // padded concat K: 2048 (h) + 192 (out_prev pad)
#define NPAD2   192         // fc2 N padded to multiple of 64

// ------------------------- device scratch (no allocs) ----------------------
__device__ __half d_Wcat[(size_t)G4 * KXP];     // [8192][2240]  fp16  ~36.7MB
__device__ __half d_Wfc1[(size_t)HID * HID];    // [2048][2048]  fp16   8MB
__device__ __half d_Wfc2[(size_t)NPAD2 * HID];  // [192][2048]   fp16  0.8MB
__device__ float  d_gbias[NCLS * G4];           // [40][8192]    fp32  1.3MB
__device__ float  d_gates[(size_t)BATCH * G4];  // [512][8192]   fp32  16MB
__device__ __half d_X[BATCH * KXP];             // [512][2240]   fp16 (h | out_prev)
__device__ float  d_cst[BATCH * HID];           // [512][2048]   fp32 cell state
__device__ __half d_t1[BATCH * HID];            // [512][2048]   fp16
__device__ unsigned g_arrive;                   // grid barrier counter

// ------------------------- weight conversion -------------------------------
__global__ void conv_wcat(const float* __restrict__ Whh, const float* __restrict__ Wih) {
    size_t idx = (size_t)blockIdx.x * 256 + threadIdx.x;
    if (idx >= (size_t)G4 * KXP) return;
    int n = (int)(idx / KXP), k = (int)(idx % KXP);
    float v = 0.f;
    if (k < HID)                 v = Whh[(size_t)n * HID + k];
    else if (k - HID < OUTD)     v = Wih[(size_t)n * WIH_COLS + (k - HID)];
    d_Wcat[idx] = __float2half(v);
}

__global__ void conv_fc1(const float* __restrict__ W) {
    size_t idx = (size_t)blockIdx.x * 256 + threadIdx.x;
    if (idx >= (size_t)HID * HID) return;
    d_Wfc1[idx] = __float2half(W[idx]);
}

__global__ void conv_fc2(const float* __restrict__ W) {
    size_t idx = (size_t)blockIdx.x * 256 + threadIdx.x;
    if (idx >= (size_t)NPAD2 * HID) return;
    int n = (int)(idx / HID), k = (int)(idx % HID);
    float v = (n < OUTD) ? W[(size_t)n * HID + k] : 0.f;
    d_Wfc2[idx] = __float2half(v);
}

// gbias[cls][n] = b_ih[n] + b_hh[n] + sum_j W_ih[n][165+j] * (W_enc[j][cls] + b_enc[j])
__global__ void gbias_k(const float* __restrict__ W_enc, const float* __restrict__ b_enc,
                        const float* __restrict__ W_ih,  const float* __restrict__ b_ih,
                        const float* __restrict__ b_hh) {
    int cls = blockIdx.y;
    int n = blockIdx.x * 256 + threadIdx.x;
    __shared__ float enc[OUTD];
    if (threadIdx.x < OUTD)
        enc[threadIdx.x] = W_enc[threadIdx.x * NCLS + cls] + b_enc[threadIdx.x];
    __syncthreads();
    float a = b_ih[n] + b_hh[n];
    const float* wrow = W_ih + (size_t)n * WIH_COLS + OUTD;
    #pragma unroll 5
    for (int j = 0; j < OUTD; j++) a += wrow[j] * enc[j];
    d_gbias[cls * G4 + n] = a;
}

// h0 = frame0 @ W_inh^T + b_inh (fp16 into X), c0 = frame0 @ W_inc^T + b_inc (fp32)
// Also resets the grid barrier counter.
__global__ void init_k(const float* __restrict__ inputs,
                       const float* __restrict__ W_inh, const float* __restrict__ b_inh,
                       const float* __restrict__ W_inc, const float* __restrict__ b_inc) {
    if (blockIdx.x == 0 && blockIdx.y == 0 && threadIdx.x == 0) g_arrive = 0;
    int b = blockIdx.y;
    int k = blockIdx.x * 256 + threadIdx.x;
    __shared__ float f0[OUTD];
    if (threadIdx.x < OUTD) f0[threadIdx.x] = inputs[b * OUTD + threadIdx.x];
    __syncthreads();
    float ah = b_inh[k], ac = b_inc[k];
    const float* wh = W_inh + (size_t)k * OUTD;
    const float* wc = W_inc + (size_t)k * OUTD;
    #pragma unroll 5
    for (int j = 0; j < OUTD; j++) { ah += f0[j] * wh[j]; ac += f0[j] * wc[j]; }
    d_cst[b * HID + k] = ac;
    d_X[b * KXP + k] = __float2half(ah);
}

// out_prev(step 0) = frame0, zero-pad cols [2048+165, 2240)
__global__ void initx_k(const float* __restrict__ inputs) {
    int b = blockIdx.x;
    int j = threadIdx.x;            // 192 threads
    float v = (j < OUTD) ? inputs[b * OUTD + j] : 0.f;
    d_X[b * KXP + HID + j] = __float2half(v);
}

// ------------------------- grid barrier ------------------------------------
__device__ __forceinline__ void grid_sync(unsigned nblocks, unsigned& ep) {
    __syncthreads();
    if (threadIdx.x == 0) {
        __threadfence();                        // release all prior writes
        atomicAdd(&g_arrive, 1u);
        unsigned want = (ep + 1u) * nblocks;
        while (*(volatile unsigned*)&g_arrive < want) { __nanosleep(64); }
        __threadfence();                        // acquire
    }
    ep++;
    __syncthreads();
}

// ------------------------- GEMM tile: mma.sync m16n8k16 --------------------
// C[128,64] block tile, 8 warps (4x2), warp tile 32x32, BK=64.
// MODE 0: gates  (A=d_X lda=KXP,  B=d_Wcat,  K=KXP, +gbias[label])
// MODE 1: fc1    (A=d_X lda=KXP,  B=d_Wfc1,  K=HID, relu+bias -> d_t1 fp16)
// MODE 2: fc2    (A=d_t1 lda=HID, B=d_Wfc2,  K=HID, +bias -> d_out & d_X outprev)
template<int MODE>
__device__ void gemm_tile(int m0, int n0,
                          const int* __restrict__ labels,
                          const float* __restrict__ bias,
                          float* __restrict__ outp, int t,
                          __half (*As)[72], __half (*Bs)[72]) {
    const __half* Ag; int lda; const __half* Bg; int ldb; int K;
    if (MODE == 0)      { Ag = d_X;  lda = KXP; Bg = d_Wcat; ldb = KXP; K = KXP; }
    else if (MODE == 1) { Ag = d_X;  lda = KXP; Bg = d_Wfc1; ldb = HID; K = HID; }
    else                { Ag = d_t1; lda = HID; Bg = d_Wfc2; ldb = HID; K = HID; }

    const int tid  = threadIdx.x;
    const int lane = tid & 31;
    const int wid  = tid >> 5;
    const int wm   = wid & 3;          // 4 warp rows of 32
    const int wn   = wid >> 2;         // 2 warp cols of 32

    float acc[2][4][4];
    #pragma unroll
    for (int i = 0; i < 2; i++)
        #pragma unroll
        for (int j = 0; j < 4; j++)
            #pragma unroll
            for (int k = 0; k < 4; k++) acc[i][j][k] = 0.f;

    const int r  = lane >> 2;          // 0..7
    const int c2 = (lane & 3) << 1;    // 0,2,4,6

    const int arow = tid >> 3;         // 0..31
    const int acol = (tid & 7) * 8;    // 0..56

    for (int kb = 0; kb < K; kb += 64) {
        #pragma unroll
        for (int i = 0; i < 4; i++) {
            int rr = arow + i * 32;
            *(uint4*)&As[rr][acol] =
                *(const uint4*)&Ag[(size_t)(m0 + rr) * lda + kb + acol];
        }
        #pragma unroll
        for (int i = 0; i < 2; i++) {
            int rr = arow + i * 32;
            *(uint4*)&Bs[rr][acol] =
                *(const uint4*)&Bg[(size_t)(n0 + rr) * ldb + kb + acol];
        }
        __syncthreads();

        #pragma unroll
        for (int ks = 0; ks < 4; ks++) {
            uint32_t af[2][4];
            #pragma unroll
            for (int mt = 0; mt < 2; mt++) {
                int rb = wm * 32 + mt * 16;
                af[mt][0] = *(const uint32_t*)&As[rb + r    ][ks * 16 + c2    ];
                af[mt][1] = *(const uint32_t*)&As[rb + r + 8][ks * 16 + c2    ];
                af[mt][2] = *(const uint32_t*)&As[rb + r    ][ks * 16 + c2 + 8];
                af[mt][3] = *(const uint32_t*)&As[rb + r + 8][ks * 16 + c2 + 8];
            }
            #pragma unroll
            for (int nt = 0; nt < 4; nt++) {
                int cb = wn * 32 + nt * 8 + (lane >> 2);
                uint32_t b0 = *(const uint32_t*)&Bs[cb][ks * 16 + c2    ];
                uint32_t b1 = *(const uint32_t*)&Bs[cb][ks * 16 + c2 + 8];
                #pragma unroll
                for (int mt = 0; mt < 2; mt++) {
                    float* c = acc[mt][nt];
                    asm volatile(
                        "mma.sync.aligned.m16n8k16.row.col.f32.f16.f16.f32 "
                        "{%0,%1,%2,%3}, {%4,%5,%6,%7}, {%8,%9}, {%0,%1,%2,%3};"
                        : "+f"(c[0]), "+f"(c[1]), "+f"(c[2]), "+f"(c[3])
                        : "r"(af[mt][0]), "r"(af[mt][1]), "r"(af[mt][2]), "r"(af[mt][3]),
                          "r"(b0), "r"(b1));
                }
            }
        }
        __syncthreads();
    }

    // ---------------- epilogue ----------------
    #pragma unroll
    for (int mt = 0; mt < 2; mt++) {
        int row0 = m0 + wm * 32 + mt * 16 + r;
        int row1 = row0 + 8;
        int lb0 = 0, lb1 = 0;
        if (MODE == 0) { lb0 = labels[row0]; lb1 = labels[row1]; }
        #pragma unroll
        for (int nt = 0; nt < 4; nt++) {
            int col0 = n0 + wn * 32 + nt * 8 + c2;
            float v00 = acc[mt][nt][0], v01 = acc[mt][nt][1];
            float v10 = acc[mt][nt][2], v11 = acc[mt][nt][3];
            if (MODE == 0) {
                d_gates[(size_t)row0 * G4 + col0    ] = v00 + d_gbias[lb0 * G4 + col0    ];
                d_gates[(size_t)row0 * G4 + col0 + 1] = v01 + d_gbias[lb0 * G4 + col0 + 1];
                d_gates[(size_t)row1 * G4 + col0    ] = v10 + d_gbias[lb1 * G4 + col0    ];
                d_gates[(size_t)row1 * G4 + col0 + 1] = v11 + d_gbias[lb1 * G4 + col0 + 1];
            } else if (MODE == 1) {
                float b0v = bias[col0], b1v = bias[col0 + 1];
                d_t1[(size_t)row0 * HID + col0    ] = __float2half(fmaxf(v00 + b0v, 0.f));
                d_t1[(size_t)row0 * HID + col0 + 1] = __float2half(fmaxf(v01 + b1v, 0.f));
                d_t1[(size_t)row1 * HID + col0    ] = __float2half(fmaxf(v10 + b0v, 0.f));
                d_t1[(size_t)row1 * HID + col0 + 1] = __float2half(fmaxf(v11 + b1v, 0.f));
            } else {
                #pragma unroll
                for (int e = 0; e < 2; e++) {
                    int col = col0 + e;
                    if (col < OUTD) {
                        float bv = bias[col];
                        float a0 = (e == 0 ? v00 : v01) + bv;
                        float a1 = (e == 0 ? v10 : v11) + bv;
                        outp[((size_t)row0 * SEQL + t) * OUTD + col] = a0;
                        outp[((size_t)row1 * SEQL + t) * OUTD + col] = a1;
                        d_X[row0 * KXP + HID + col] = __float2half(a0);
                        d_X[row1 * KXP + HID + col] = __float2half(a1);
                    }
                }
            }
        }
    }
}

// ------------------------- persistent kernel -------------------------------
__global__ void __launch_bounds__(256, 2)
rnn_persist(const int* __restrict__ labels,
            const float* __restrict__ b_fc1, const float* __restrict__ b_fc2,
            float* __restrict__ out, unsigned nblocks) {
    __shared__ __align__(16) __half As[128][72];
    __shared__ __align__(16) __half Bs[64][72];

    unsigned ep = 0;
    const unsigned nthreads = nblocks * 256;
    const unsigned gtid = blockIdx.x * 256 + threadIdx.x;

    for (int t = 0; t < SEQL; t++) {
        // ---- gates GEMM: 512 tiles (4 x 128) ----
        for (unsigned tile = blockIdx.x; tile < 512; tile += nblocks)
            gemm_tile<0>((tile >> 7) * 128, (tile & 127) * 64,
                         labels, nullptr, nullptr, 0, As, Bs);
        grid_sync(nblocks, ep);

        // ---- LSTM cell elementwise ----
        for (unsigned idx = gtid; idx < BATCH * HID; idx += nthreads) {
            int b = idx >> 11, k = idx & 2047;
            size_t base = (size_t)b * G4 + k;
            float gi = d_gates[base];
            float gf = d_gates[base + 2048];
            float gg = d_gates[base + 4096];
            float go = d_gates[base + 6144];
            float c = d_cst[idx];
            float si = 1.f / (1.f + expf(-gi));
            float sf = 1.f / (1.f + expf(-gf));
            float so = 1.f / (1.f + expf(-go));
            c = sf * c + si * tanhf(gg);
            float h = so * tanhf(c);
            d_cst[idx] = c;
            d_X[b * KXP + k] = __float2half(h);
        }
        grid_sync(nblocks, ep);

        // ---- fc1 GEMM + relu: 128 tiles (4 x 32) ----
        for (unsigned tile = blockIdx.x; tile < 128; tile += nblocks)
            gemm_tile<1>((tile >> 5) * 128, (tile & 31) * 64,
                         nullptr, b_fc1, nullptr, 0, As, Bs);
        grid_sync(nblocks, ep);

        // ---- fc2 GEMM: 12 tiles (4 x 3) ----
        for (unsigned tile = blockIdx.x; tile < 12; tile += nblocks)
            gemm_tile<2>((tile / 3) * 128, (tile % 3) * 64,
                         nullptr, b_fc2, out, t, As, Bs);
        grid_sync(nblocks, ep);
    }
}

// ------------------------- launch ------------------------------------------
extern "C" void kernel_launch(void* const* d_in, const int* in_sizes, int n_in,
                              void* d_out, int out_size) {
    const float* inputs = (const float*)d_in[0];
    const int*   labels = (const int*)  d_in[1];
    // d_in[2] = length (constant 240, hardcoded)
    const float* W_enc  = (const float*)d_in[3];
    const float* b_enc  = (const float*)d_in[4];
    const float* W_ih   = (const float*)d_in[5];
    const float* b_ih   = (const float*)d_in[6];
    const float* W_hh   = (const float*)d_in[7];
    const float* b_hh   = (const float*)d_in[8];
    const float* W_fc1  = (const float*)d_in[9];
    const float* b_fc1  = (const float*)d_in[10];
    const float* W_fc2  = (const float*)d_in[11];
    const float* b_fc2  = (const float*)d_in[12];
    const float* W_inh  = (const float*)d_in[13];
    const float* b_inh  = (const float*)d_in[14];
    const float* W_inc  = (const float*)d_in[15];
    const float* b_inc  = (const float*)d_in[16];
    float* out = (float*)d_out;

    // Resident grid size: guaranteed co-resident blocks for the software barrier.
    int dev = 0, sms = 0, occ = 0;
    cudaGetDevice(&dev);
    cudaDeviceGetAttribute(&sms, cudaDevAttrMultiProcessorCount, dev);
    cudaOccupancyMaxActiveBlocksPerMultiprocessor(&occ, rnn_persist, 256, 0);
    if (occ < 1) occ = 1;
    unsigned nblocks = (unsigned)(sms * occ);

    // one-time (per launch) precompute — 6 graph nodes
    conv_wcat<<<(int)(((size_t)G4 * KXP + 255) / 256), 256>>>(W_hh, W_ih);
    conv_fc1<<<(HID * HID) / 256, 256>>>(W_fc1);
    conv_fc2<<<(NPAD2 * HID) / 256, 256>>>(W_fc2);
    gbias_k<<<dim3(G4 / 256, NCLS), 256>>>(W_enc, b_enc, W_ih, b_ih, b_hh);
    init_k<<<dim3(HID / 256, BATCH), 256>>>(inputs, W_inh, b_inh, W_inc, b_inc);
    initx_k<<<BATCH, 192>>>(inputs);

    // all 240 steps in one persistent kernel — 1 graph node
    rnn_persist<<<nblocks, 256>>>(labels, b_fc1, b_fc2, out, nblocks);
}

// round 5
// speedup vs baseline: 1.0968x; 1.0968x over previous
#include <cuda_runtime.h>
#include <cuda_fp16.h>
#include <math.h>
#include <stdint.h>

// ---------------------------------------------------------------------------
// DecoderRNN: 240-step LSTM decoder, B=512, H=2048, OUT=165, NCLS=40
// Persistent kernel, fp16 tensor-core GEMMs (mma.sync m16n8k16):
//   - 128x128 block tiles, BK=32, cp.async double-buffered, ldmatrix fragments
//   - gate columns interleaved (col = 4k+gate): LSTM cell fused into the
//     gates-GEMM epilogue
//   - PING-PONG X buffers: gates read X[t&1], cell/fc2 write X[1-(t&1)]
//     (fixes the R4 read/write race on h)
// ---------------------------------------------------------------------------

#define BATCH   512
#define HID     2048
#define G4      8192        // 4*HID
#define OUTD    165
#define NCLS    40
#define SEQL    240
#define WIH_COLS 330        // 2*OUTD
#define KXP     2240        // padded concat K: 2048 (h) + 192 (out_prev pad)
#define NPAD2   256         // fc2 N padded to multiple of 128

#define ASTR    40          // smem row stride in halves (32 + 8 pad)
#define STAGE_BYTES (128 * ASTR * 2)

// ------------------------- device scratch (no allocs) ----------------------
__device__ __half d_Wcat[(size_t)G4 * KXP];     // [8192][2240] interleaved rows
__device__ __half d_Wfc1[(size_t)HID * HID];    // [2048][2048]
__device__ __half d_Wfc2[(size_t)NPAD2 * HID];  // [256][2048] zero-padded
__device__ float  d_gbias[NCLS * G4];           // [40][8192] interleaved cols
__device__ __half d_Xbuf[2][BATCH * KXP];       // ping-pong (h | out_prev)
__device__ float  d_cst[BATCH * HID];           // [512][2048] fp32 cell state
__device__ __half d_t1[BATCH * HID];            // [512][2048]
__device__ unsigned g_arrive;                   // grid barrier counter

// ------------------------- weight conversion -------------------------------
// Interleave map: new row n' = 4k+g  <->  original n = g*2048 + k
__global__ void conv_wcat(const float* __restrict__ Whh, const float* __restrict__ Wih) {
    size_t idx = (size_t)blockIdx.x * 256 + threadIdx.x;
    if (idx >= (size_t)G4 * KXP) return;
    int np = (int)(idx / KXP), k = (int)(idx % KXP);
    int n = (np & 3) * HID + (np >> 2);         // original gate row
    float v = 0.f;
    if (k < HID)                 v = Whh[(size_t)n * HID + k];
    else if (k - HID < OUTD)     v = Wih[(size_t)n * WIH_COLS + (k - HID)];
    d_Wcat[idx] = __float2half(v);
}

__global__ void conv_fc1(const float* __restrict__ W) {
    size_t idx = (size_t)blockIdx.x * 256 + threadIdx.x;
    if (idx >= (size_t)HID * HID) return;
    d_Wfc1[idx] = __float2half(W[idx]);
}

__global__ void conv_fc2(const float* __restrict__ W) {
    size_t idx = (size_t)blockIdx.x * 256 + threadIdx.x;
    if (idx >= (size_t)NPAD2 * HID) return;
    int n = (int)(idx / HID), k = (int)(idx % HID);
    float v = (n < OUTD) ? W[(size_t)n * HID + k] : 0.f;
    d_Wfc2[idx] = __float2half(v);
}

// gbias[cls][n'] = b_ih[n] + b_hh[n] + sum_j W_ih[n][165+j]*(W_enc[j][cls]+b_enc[j])
__global__ void gbias_k(const float* __restrict__ W_enc, const float* __restrict__ b_enc,
                        const float* __restrict__ W_ih,  const float* __restrict__ b_ih,
                        const float* __restrict__ b_hh) {
    int cls = blockIdx.y;
    int n = blockIdx.x * 256 + threadIdx.x;     // original gate row
    __shared__ float enc[OUTD];
    if (threadIdx.x < OUTD)
        enc[threadIdx.x] = W_enc[threadIdx.x * NCLS + cls] + b_enc[threadIdx.x];
    __syncthreads();
    float a = b_ih[n] + b_hh[n];
    const float* wrow = W_ih + (size_t)n * WIH_COLS + OUTD;
    #pragma unroll 5
    for (int j = 0; j < OUTD; j++) a += wrow[j] * enc[j];
    int np = 4 * (n & (HID - 1)) + (n >> 11);   // interleaved position
    d_gbias[cls * G4 + np] = a;
}

// h0/c0 init into X[0]; also resets the grid barrier counter
__global__ void init_k(const float* __restrict__ inputs,
                       const float* __restrict__ W_inh, const float* __restrict__ b_inh,
                       const float* __restrict__ W_inc, const float* __restrict__ b_inc) {
    if (blockIdx.x == 0 && blockIdx.y == 0 && threadIdx.x == 0) g_arrive = 0;
    int b = blockIdx.y;
    int k = blockIdx.x * 256 + threadIdx.x;
    __shared__ float f0[OUTD];
    if (threadIdx.x < OUTD) f0[threadIdx.x] = inputs[b * OUTD + threadIdx.x];
    __syncthreads();
    float ah = b_inh[k], ac = b_inc[k];
    const float* wh = W_inh + (size_t)k * OUTD;
    const float* wc = W_inc + (size_t)k * OUTD;
    #pragma unroll 5
    for (int j = 0; j < OUTD; j++) { ah += f0[j] * wh[j]; ac += f0[j] * wc[j]; }
    d_cst[b * HID + k] = ac;
    d_Xbuf[0][b * KXP + k] = __float2half(ah);
}

// out_prev(step 0) = frame0 into X[0]; zero-pad tails of BOTH buffers
__global__ void initx_k(const float* __restrict__ inputs) {
    int b = blockIdx.x;
    int j = threadIdx.x;            // 192 threads
    float v = (j < OUTD) ? inputs[b * OUTD + j] : 0.f;
    d_Xbuf[0][b * KXP + HID + j] = __float2half(v);
    if (j >= OUTD) d_Xbuf[1][b * KXP + HID + j] = __float2half(0.f);
}

// ------------------------- helpers -----------------------------------------
__device__ __forceinline__ void cpa16(uint32_t s, const void* g) {
    asm volatile("cp.async.cg.shared.global [%0], [%1], 16;" :: "r"(s), "l"(g));
}
__device__ __forceinline__ void cpa_commit() {
    asm volatile("cp.async.commit_group;");
}
template<int N> __device__ __forceinline__ void cpa_wait() {
    asm volatile("cp.async.wait_group %0;" :: "n"(N));
}
__device__ __forceinline__ float sigf(float x) {
    return __fdividef(1.f, 1.f + __expf(-x));
}
__device__ __forceinline__ float tanhf_(float x) {
    float e = __expf(-2.f * x);
    return __fdividef(1.f - e, 1.f + e);
}

__device__ __forceinline__ void grid_sync(unsigned nblocks, unsigned& ep) {
    __syncthreads();
    if (threadIdx.x == 0) {
        __threadfence();
        atomicAdd(&g_arrive, 1u);
        unsigned want = (ep + 1u) * nblocks;
        while (*(volatile unsigned*)&g_arrive < want) { __nanosleep(64); }
        __threadfence();
    }
    ep++;
    __syncthreads();
}

// ------------------------- GEMM tile ---------------------------------------
// C[128,128] = A[128,K] @ B[128,K]^T, BK=32, 8 warps (2m x 4n), warp 64x32.
// MODE 0: gates (A=Xcur K=KXP, B=d_Wcat) + fused LSTM cell -> Xnxt h, d_cst
// MODE 1: fc1   (A=Xnxt K=HID, B=d_Wfc1) + relu+bias -> d_t1
// MODE 2: fc2   (A=d_t1 K=HID, B=d_Wfc2) + bias -> out & Xnxt out_prev
template<int MODE>
__device__ void gemm_tile(int m0, int n0,
                          const __half* __restrict__ Ain,
                          __half* __restrict__ Xw,
                          const int* __restrict__ labels,
                          const float* __restrict__ bias,
                          float* __restrict__ outp, int t,
                          uint32_t saA, uint32_t saB) {
    const __half* Ag = Ain; int lda; const __half* Bg; int ldb; int K;
    if (MODE == 0)      { lda = KXP; Bg = d_Wcat; ldb = KXP; K = KXP; }
    else if (MODE == 1) { lda = KXP; Bg = d_Wfc1; ldb = HID; K = HID; }
    else                { lda = HID; Bg = d_Wfc2; ldb = HID; K = HID; }
    const int nk = K / 32;

    const int tid  = threadIdx.x;
    const int lane = tid & 31;
    const int wid  = tid >> 5;
    const int wm   = wid & 1;          // 2 m-warps of 64
    const int wn   = wid >> 1;         // 4 n-warps of 32

    // cp.async addressing: each thread loads 2 chunks of 16B for A and B
    const int ldrow = tid >> 2;                 // 0..63
    const int ldcol = (tid & 3) * 8;            // halves
    const uint32_t offA0 = (uint32_t)((ldrow * ASTR + ldcol) * 2);
    const uint32_t offA1 = (uint32_t)(((ldrow + 64) * ASTR + ldcol) * 2);
    const __half* gA0 = Ag + (size_t)(m0 + ldrow) * lda + ldcol;
    const __half* gA1 = Ag + (size_t)(m0 + ldrow + 64) * lda + ldcol;
    const __half* gB0 = Bg + (size_t)(n0 + ldrow) * ldb + ldcol;
    const __half* gB1 = Bg + (size_t)(n0 + ldrow + 64) * ldb + ldcol;

    // ldmatrix addressing (lane-specific bases, stage 0)
    const uint32_t aBase = saA + (uint32_t)(((wm * 64 + (lane & 15)) * ASTR
                                             + (lane >> 4) * 8) * 2);
    const uint32_t bBase = saB + (uint32_t)(((wn * 32 + (lane & 7)) * ASTR
                                             + ((lane >> 3) & 1) * 8) * 2);

    float acc[4][4][4];
    #pragma unroll
    for (int i = 0; i < 4; i++)
        #pragma unroll
        for (int j = 0; j < 4; j++)
            #pragma unroll
            for (int k = 0; k < 4; k++) acc[i][j][k] = 0.f;

    // prologue: stage 0 (A and B share the same smem layout/offsets)
    cpa16(saA + offA0, gA0); cpa16(saA + offA1, gA1);
    cpa16(saB + offA0, gB0); cpa16(saB + offA1, gB1);
    cpa_commit();

    int s = 0;
    for (int kb = 0; kb < nk; kb++) {
        if (kb + 1 < nk) {
            int ns = s ^ 1;
            int ko = (kb + 1) * 32;
            cpa16(saA + ns * STAGE_BYTES + offA0, gA0 + ko);
            cpa16(saA + ns * STAGE_BYTES + offA1, gA1 + ko);
            cpa16(saB + ns * STAGE_BYTES + offA0, gB0 + ko);
            cpa16(saB + ns * STAGE_BYTES + offA1, gB1 + ko);
            cpa_commit();
            cpa_wait<1>();
        } else {
            cpa_wait<0>();
        }
        __syncthreads();

        const uint32_t aS = aBase + (uint32_t)(s * STAGE_BYTES);
        const uint32_t bS = bBase + (uint32_t)(s * STAGE_BYTES);
        #pragma unroll
        for (int ks = 0; ks < 2; ks++) {
            uint32_t af[4][4];
            #pragma unroll
            for (int mt = 0; mt < 4; mt++) {
                uint32_t ad = aS + (uint32_t)((mt * 16 * ASTR + ks * 16) * 2);
                asm volatile("ldmatrix.sync.aligned.m8n8.x4.shared.b16 "
                             "{%0,%1,%2,%3}, [%4];"
                             : "=r"(af[mt][0]), "=r"(af[mt][1]),
                               "=r"(af[mt][2]), "=r"(af[mt][3]) : "r"(ad));
            }
            #pragma unroll
            for (int nt = 0; nt < 4; nt++) {
                uint32_t bd = bS + (uint32_t)((nt * 8 * ASTR + ks * 16) * 2);
                uint32_t b0, b1;
                asm volatile("ldmatrix.sync.aligned.m8n8.x2.shared.b16 "
                             "{%0,%1}, [%2];"
                             : "=r"(b0), "=r"(b1) : "r"(bd));
                #pragma unroll
                for (int mt = 0; mt < 4; mt++) {
                    float* c = acc[mt][nt];
                    asm volatile(
                        "mma.sync.aligned.m16n8k16.row.col.f32.f16.f16.f32 "
                        "{%0,%1,%2,%3}, {%4,%5,%6,%7}, {%8,%9}, {%0,%1,%2,%3};"
                        : "+f"(c[0]), "+f"(c[1]), "+f"(c[2]), "+f"(c[3])
                        : "r"(af[mt][0]), "r"(af[mt][1]),
                          "r"(af[mt][2]), "r"(af[mt][3]), "r"(b0), "r"(b1));
                }
            }
        }
        s ^= 1;
        __syncthreads();
    }

    // ---------------- epilogue ----------------
    const int r  = lane >> 2;          // 0..7
    const int c2 = (lane & 3) << 1;    // 0,2,4,6
    #pragma unroll
    for (int mt = 0; mt < 4; mt++) {
        int row0 = m0 + wm * 64 + mt * 16 + r;
        int row1 = row0 + 8;
        int lb0 = 0, lb1 = 0;
        if (MODE == 0) { lb0 = labels[row0]; lb1 = labels[row1]; }
        #pragma unroll
        for (int nt = 0; nt < 4; nt++) {
            int col0 = n0 + wn * 32 + nt * 8 + c2;
            float v00 = acc[mt][nt][0], v01 = acc[mt][nt][1];
            float v10 = acc[mt][nt][2], v11 = acc[mt][nt][3];
            if (MODE == 0) {
                // add per-class gate bias (interleaved layout)
                v00 += d_gbias[lb0 * G4 + col0];
                v01 += d_gbias[lb0 * G4 + col0 + 1];
                v10 += d_gbias[lb1 * G4 + col0];
                v11 += d_gbias[lb1 * G4 + col0 + 1];
                // cols interleaved 4k+gate: even lane holds (i,f), odd (g,o)
                float p00 = __shfl_xor_sync(0xffffffffu, v00, 1);
                float p01 = __shfl_xor_sync(0xffffffffu, v01, 1);
                float p10 = __shfl_xor_sync(0xffffffffu, v10, 1);
                float p11 = __shfl_xor_sync(0xffffffffu, v11, 1);
                if ((lane & 1) == 0) {
                    // this lane: v00=i, v01=f; partner: p00=g, p01=o
                    int k = col0 >> 2;
                    float cs0 = d_cst[row0 * HID + k];
                    float cn0 = sigf(v01) * cs0 + sigf(v00) * tanhf_(p00);
                    d_cst[row0 * HID + k] = cn0;
                    Xw[row0 * KXP + k] = __float2half(sigf(p01) * tanhf_(cn0));
                    float cs1 = d_cst[row1 * HID + k];
                    float cn1 = sigf(v11) * cs1 + sigf(v10) * tanhf_(p10);
                    d_cst[row1 * HID + k] = cn1;
                    Xw[row1 * KXP + k] = __float2half(sigf(p11) * tanhf_(cn1));
                }
            } else if (MODE == 1) {
                float b0v = bias[col0], b1v = bias[col0 + 1];
                d_t1[(size_t)row0 * HID + col0    ] = __float2half(fmaxf(v00 + b0v, 0.f));
                d_t1[(size_t)row0 * HID + col0 + 1] = __float2half(fmaxf(v01 + b1v, 0.f));
                d_t1[(size_t)row1 * HID + col0    ] = __float2half(fmaxf(v10 + b0v, 0.f));
                d_t1[(size_t)row1 * HID + col0 + 1] = __float2half(fmaxf(v11 + b1v, 0.f));
            } else {
                #pragma unroll
                for (int e = 0; e < 2; e++) {
                    int col = col0 + e;
                    if (col < OUTD) {
                        float bv = bias[col];
                        float a0 = (e == 0 ? v00 : v01) + bv;
                        float a1 = (e == 0 ? v10 : v11) + bv;
                        outp[((size_t)row0 * SEQL + t) * OUTD + col] = a0;
                        outp[((size_t)row1 * SEQL + t) * OUTD + col] = a1;
                        Xw[row0 * KXP + HID + col] = __float2half(a0);
                        Xw[row1 * KXP + HID + col] = __float2half(a1);
                    }
                }
            }
        }
    }
}

// ------------------------- persistent kernel -------------------------------
__global__ void __launch_bounds__(256, 2)
rnn_persist(const int* __restrict__ labels,
            const float* __restrict__ b_fc1, const float* __restrict__ b_fc2,
            float* __restrict__ out, unsigned nblocks) {
    __shared__ __align__(16) __half As[2][128][ASTR];
    __shared__ __align__(16) __half Bs[2][128][ASTR];
    const uint32_t saA = (uint32_t)__cvta_generic_to_shared(&As[0][0][0]);
    const uint32_t saB = (uint32_t)__cvta_generic_to_shared(&Bs[0][0][0]);

    unsigned ep = 0;
    const unsigned bx = blockIdx.x;

    for (int t = 0; t < SEQL; t++) {
        __half* Xcur = d_Xbuf[t & 1];
        __half* Xnxt = d_Xbuf[(t & 1) ^ 1];

        // gates GEMM + fused cell: 4 m-tiles x 64 n-tiles = 256 tiles
        for (unsigned tile = bx; tile < 256; tile += nblocks)
            gemm_tile<0>((tile >> 6) * 128, (tile & 63) * 128,
                         Xcur, Xnxt, labels, nullptr, nullptr, 0, saA, saB);
        grid_sync(nblocks, ep);

        // fc1 + relu: 4 x 16 = 64 tiles (reads NEW h from Xnxt)
        for (unsigned tile = bx; tile < 64; tile += nblocks)
            gemm_tile<1>((tile >> 4) * 128, (tile & 15) * 128,
                         Xnxt, nullptr, nullptr, b_fc1, nullptr, 0, saA, saB);
        grid_sync(nblocks, ep);

        // fc2: 4 x 2 = 8 tiles (writes out_prev into Xnxt tail)
        for (unsigned tile = bx; tile < 8; tile += nblocks)
            gemm_tile<2>((tile >> 1) * 128, (tile & 1) * 128,
                         d_t1, Xnxt, nullptr, b_fc2, out, t, saA, saB);
        grid_sync(nblocks, ep);
    }
}

// ------------------------- launch ------------------------------------------
extern "C" void kernel_launch(void* const* d_in, const int* in_sizes, int n_in,
                              void* d_out, int out_size) {
    const float* inputs = (const float*)d_in[0];
    const int*   labels = (const int*)  d_in[1];
    // d_in[2] = length (constant 240)
    const float* W_enc  = (const float*)d_in[3];
    const float* b_enc  = (const float*)d_in[4];
    const float* W_ih   = (const float*)d_in[5];
    const float* b_ih   = (const float*)d_in[6];
    const float* W_hh   = (const float*)d_in[7];
    const float* b_hh   = (const float*)d_in[8];
    const float* W_fc1  = (const float*)d_in[9];
    const float* b_fc1  = (const float*)d_in[10];
    const float* W_fc2  = (const float*)d_in[11];
    const float* b_fc2  = (const float*)d_in[12];
    const float* W_inh  = (const float*)d_in[13];
    const float* b_inh  = (const float*)d_in[14];
    const float* W_inc  = (const float*)d_in[15];
    const float* b_inc  = (const float*)d_in[16];
    float* out = (float*)d_out;

    int dev = 0, sms = 0, occ = 0;
    cudaGetDevice(&dev);
    cudaDeviceGetAttribute(&sms, cudaDevAttrMultiProcessorCount, dev);
    cudaOccupancyMaxActiveBlocksPerMultiprocessor(&occ, rnn_persist, 256, 0);
    if (occ < 1) occ = 1;
    unsigned nblocks = (unsigned)(sms * occ);

    conv_wcat<<<(int)(((size_t)G4 * KXP + 255) / 256), 256>>>(W_hh, W_ih);
    conv_fc1<<<(HID * HID) / 256, 256>>>(W_fc1);
    conv_fc2<<<(NPAD2 * HID) / 256, 256>>>(W_fc2);
    gbias_k<<<dim3(G4 / 256, NCLS), 256>>>(W_enc, b_enc, W_ih, b_ih, b_hh);
    init_k<<<dim3(HID / 256, BATCH), 256>>>(inputs, W_inh, b_inh, W_inc, b_inc);
    initx_k<<<BATCH, 192>>>(inputs);

    rnn_persist<<<nblocks, 256>>>(labels, b_fc1, b_fc2, out, nblocks);
}

// round 6
// speedup vs baseline: 1.3369x; 1.2189x over previous
#include <cuda_runtime.h>
#include <cuda_fp16.h>
#include <math.h>
#include <stdint.h>

// ---------------------------------------------------------------------------
// DecoderRNN: 240-step LSTM decoder, B=512, H=2048, OUT=165, NCLS=40
// Persistent kernel, fp16 mma.sync GEMMs.
// R6: 4-stage cp.async pipeline (BK=32), 1 syncthreads/k-iter, per-phase tile
// shapes giving single-wave execution at 1 block/SM (smem-pinned occupancy):
//   gates 128x256 (128 tiles), fc1 64x128 (128 tiles), fc2 64x64 (32 tiles).
// Setup merged to 2 kernels so ncu -s5 -c1 captures rnn_persist.
// ---------------------------------------------------------------------------

#define BATCH   512
#define HID     2048
#define G4      8192        // 4*HID
#define OUTD    165
#define NCLS    40
#define SEQL    240
#define WIH_COLS 330        // 2*OUTD
#define KXP     2240        // padded concat K: 2048 (h) + 192 (out_prev pad)
#define NPAD2   256         // fc2 N padded

#define ROWH    40          // smem row stride in halves (32 + 8 pad)
#define STG_A_BYTES (128 * ROWH * 2)          // 10240
#define STG_BYTES   ((128 + 256) * ROWH * 2)  // 30720 per stage (A then B)
#define NSTAGE  4
#define SMEM_TOTAL (NSTAGE * STG_BYTES)       // 122880

// ------------------------- device scratch (no allocs) ----------------------
__device__ __half d_Wcat[(size_t)G4 * KXP];     // [8192][2240] interleaved rows
__device__ __half d_Wfc1[(size_t)HID * HID];    // [2048][2048]
__device__ __half d_Wfc2[(size_t)NPAD2 * HID];  // [256][2048] zero-padded
__device__ float  d_gbias[NCLS * G4];           // [40][8192] interleaved cols
__device__ __half d_Xbuf[2][BATCH * KXP];       // ping-pong (h | out_prev)
__device__ float  d_cst[BATCH * HID];           // fp32 cell state
__device__ __half d_t1[BATCH * HID];
__device__ unsigned g_arrive;                   // grid barrier counter

// ------------------------- setup kernel A: Wcat convert --------------------
// Interleave map: new row n' = 4k+g  <->  original n = g*2048 + k
__global__ void setupA(const float* __restrict__ Whh, const float* __restrict__ Wih) {
    size_t idx = (size_t)blockIdx.x * 256 + threadIdx.x;
    if (idx >= (size_t)G4 * KXP) return;
    int np = (int)(idx / KXP), k = (int)(idx % KXP);
    int n = (np & 3) * HID + (np >> 2);
    float v = 0.f;
    if (k < HID)                 v = Whh[(size_t)n * HID + k];
    else if (k - HID < OUTD)     v = Wih[(size_t)n * WIH_COLS + (k - HID)];
    d_Wcat[idx] = __float2half(v);
}

// ------------------------- setup kernel B: everything else -----------------
// blocks [0,16384): fc1 conv | [16384,18432): fc2 conv | [18432,19712): gbias
// [19712,23808): h0/c0 init | [23808,24320): out_prev init + pad zeroing
#define SB_FC1  16384
#define SB_FC2  (SB_FC1 + 2048)
#define SB_GB   (SB_FC2 + 1280)
#define SB_INIT (SB_GB + 4096)
#define SB_TOT  (SB_INIT + 512)
__global__ void setupB(const float* __restrict__ inputs,
                       const float* __restrict__ W_enc, const float* __restrict__ b_enc,
                       const float* __restrict__ W_ih,  const float* __restrict__ b_ih,
                       const float* __restrict__ b_hh,
                       const float* __restrict__ W_fc1,
                       const float* __restrict__ W_fc2,
                       const float* __restrict__ W_inh, const float* __restrict__ b_inh,
                       const float* __restrict__ W_inc, const float* __restrict__ b_inc) {
    int bid = blockIdx.x;
    int tid = threadIdx.x;
    if (bid == 0 && tid == 0) g_arrive = 0;

    if (bid < SB_FC1) {
        size_t idx = (size_t)bid * 256 + tid;
        d_Wfc1[idx] = __float2half(W_fc1[idx]);
    } else if (bid < SB_FC2) {
        size_t idx = (size_t)(bid - SB_FC1) * 256 + tid;
        int n = (int)(idx / HID), k = (int)(idx % HID);
        d_Wfc2[idx] = __float2half(n < OUTD ? W_fc2[(size_t)n * HID + k] : 0.f);
    } else if (bid < SB_GB) {
        int q = bid - SB_FC2;
        int cls = q >> 5;
        int n = (q & 31) * 256 + tid;           // original gate row
        __shared__ float enc[OUTD];
        if (tid < OUTD) enc[tid] = W_enc[tid * NCLS + cls] + b_enc[tid];
        __syncthreads();
        float a = b_ih[n] + b_hh[n];
        const float* wrow = W_ih + (size_t)n * WIH_COLS + OUTD;
        #pragma unroll 5
        for (int j = 0; j < OUTD; j++) a += wrow[j] * enc[j];
        int np = 4 * (n & (HID - 1)) + (n >> 11);
        d_gbias[cls * G4 + np] = a;
    } else if (bid < SB_INIT) {
        int q = bid - SB_GB;
        int b = q >> 3;
        int k = (q & 7) * 256 + tid;
        __shared__ float f0[OUTD];
        if (tid < OUTD) f0[tid] = inputs[b * OUTD + tid];
        __syncthreads();
        float ah = b_inh[k], ac = b_inc[k];
        const float* wh = W_inh + (size_t)k * OUTD;
        const float* wc = W_inc + (size_t)k * OUTD;
        #pragma unroll 5
        for (int j = 0; j < OUTD; j++) { ah += f0[j] * wh[j]; ac += f0[j] * wc[j]; }
        d_cst[b * HID + k] = ac;
        d_Xbuf[0][b * KXP + k] = __float2half(ah);
    } else {
        int b = bid - SB_INIT;
        int j = tid;
        if (j < KXP - HID) {
            float v = (j < OUTD) ? inputs[b * OUTD + j] : 0.f;
            d_Xbuf[0][b * KXP + HID + j] = __float2half(v);
            if (j >= OUTD) d_Xbuf[1][b * KXP + HID + j] = __float2half(0.f);
        }
    }
}

// ------------------------- helpers -----------------------------------------
__device__ __forceinline__ void cpa16(uint32_t s, const void* g) {
    asm volatile("cp.async.cg.shared.global [%0], [%1], 16;" :: "r"(s), "l"(g));
}
__device__ __forceinline__ void cpa_commit() {
    asm volatile("cp.async.commit_group;");
}
template<int N> __device__ __forceinline__ void cpa_wait() {
    asm volatile("cp.async.wait_group %0;" :: "n"(N));
}
__device__ __forceinline__ float sigf(float x) {
    return __fdividef(1.f, 1.f + __expf(-x));
}
__device__ __forceinline__ float tanhf_(float x) {
    float e = __expf(-2.f * x);
    return __fdividef(1.f - e, 1.f + e);
}
__device__ __forceinline__ void grid_sync(unsigned nblocks, unsigned& ep) {
    __syncthreads();
    if (threadIdx.x == 0) {
        __threadfence();
        atomicAdd(&g_arrive, 1u);
        unsigned want = (ep + 1u) * nblocks;
        while (*(volatile unsigned*)&g_arrive < want) { __nanosleep(64); }
        __threadfence();
    }
    ep++;
    __syncthreads();
}

// ------------------------- GEMM tile ---------------------------------------
// C[BM,BN] = A[BM,K] @ B[BN,K]^T. 8 warps as 2m x 4n; warp tile (BM/2)x(BN/4).
// 4-stage cp.async pipeline, BK=32, one __syncthreads per k-iter.
// MODE 0: gates (BM=128,BN=256) + fused LSTM cell -> Xw h, d_cst
// MODE 1: fc1   (BM=64, BN=128) + relu+bias -> d_t1
// MODE 2: fc2   (BM=64, BN=64)  + bias -> out & Xw out_prev tail
template<int MODE, int BM, int BN>
__device__ void gemm_tile(int m0, int n0,
                          const __half* __restrict__ Ain,
                          __half* __restrict__ Xw,
                          const int* __restrict__ labels,
                          const float* __restrict__ bias,
                          float* __restrict__ outp, int t,
                          uint32_t sa) {
    constexpr int MT = BM / 32;           // m16 frags per warp
    constexpr int NT = BN / 32;           // n8 frags per warp
    constexpr int WMr = BM / 2;
    constexpr int WNr = BN / 4;
    constexpr int CHUNKS = (BM + BN) * 4; // 16B chunks per stage

    const __half* Ag = Ain; int lda; const __half* Bg; int ldb; int K;
    if (MODE == 0)      { lda = KXP; Bg = d_Wcat; ldb = KXP; K = KXP; }
    else if (MODE == 1) { lda = KXP; Bg = d_Wfc1; ldb = HID; K = HID; }
    else                { lda = HID; Bg = d_Wfc2; ldb = HID; K = HID; }
    const int nk = K / 32;

    const int tid  = threadIdx.x;
    const int lane = tid & 31;
    const int wid  = tid >> 5;
    const int wm   = wid & 1;
    const int wn   = wid >> 1;

    float acc[MT][NT][4];
    #pragma unroll
    for (int i = 0; i < MT; i++)
        #pragma unroll
        for (int j = 0; j < NT; j++)
            #pragma unroll
            for (int k = 0; k < 4; k++) acc[i][j][k] = 0.f;

    // stage loader: CHUNKS 16B chunks, A rows first then B rows
    auto load_stage = [&](int st, int kb) {
        const int ko = kb * 32;
        uint32_t base = sa + st * STG_BYTES;
        #pragma unroll
        for (int c = tid; c < CHUNKS; c += 256) {
            int row = c >> 2;
            int k8 = (c & 3) * 8;
            if (row < BM) {
                cpa16(base + (uint32_t)((row * ROWH + k8) * 2),
                      Ag + (size_t)(m0 + row) * lda + ko + k8);
            } else {
                int br = row - BM;
                cpa16(base + STG_A_BYTES + (uint32_t)((br * ROWH + k8) * 2),
                      Bg + (size_t)(n0 + br) * ldb + ko + k8);
            }
        }
    };

    // ldmatrix lane bases (within a stage)
    const uint32_t aOff = (uint32_t)(((wm * WMr + (lane & 15)) * ROWH
                                      + (lane >> 4) * 8) * 2);
    const uint32_t bOff = (uint32_t)(((wn * WNr + (lane & 15)) * ROWH
                                      + (lane >> 4) * 8) * 2);

    // prologue: stages 0..2
    load_stage(0, 0); cpa_commit();
    load_stage(1, 1); cpa_commit();
    load_stage(2, 2); cpa_commit();

    for (int kb = 0; kb < nk; kb++) {
        cpa_wait<2>();
        __syncthreads();

        const int st = kb & 3;
        const uint32_t aS = sa + st * STG_BYTES + aOff;
        const uint32_t bS = sa + st * STG_BYTES + STG_A_BYTES + bOff;

        #pragma unroll
        for (int ks = 0; ks < 2; ks++) {
            uint32_t af[MT][4];
            #pragma unroll
            for (int mt = 0; mt < MT; mt++) {
                uint32_t ad = aS + (uint32_t)((mt * 16 * ROWH + ks * 16) * 2);
                asm volatile("ldmatrix.sync.aligned.m8n8.x4.shared.b16 "
                             "{%0,%1,%2,%3}, [%4];"
                             : "=r"(af[mt][0]), "=r"(af[mt][1]),
                               "=r"(af[mt][2]), "=r"(af[mt][3]) : "r"(ad));
            }
            uint32_t bb[NT][2];
            #pragma unroll
            for (int np = 0; np < NT / 2; np++) {
                uint32_t bd = bS + (uint32_t)((np * 16 * ROWH + ks * 16) * 2);
                asm volatile("ldmatrix.sync.aligned.m8n8.x4.shared.b16 "
                             "{%0,%1,%2,%3}, [%4];"
                             : "=r"(bb[2*np][0]), "=r"(bb[2*np+1][0]),
                               "=r"(bb[2*np][1]), "=r"(bb[2*np+1][1]) : "r"(bd));
            }
            #pragma unroll
            for (int nt = 0; nt < NT; nt++) {
                #pragma unroll
                for (int mt = 0; mt < MT; mt++) {
                    float* c = acc[mt][nt];
                    asm volatile(
                        "mma.sync.aligned.m16n8k16.row.col.f32.f16.f16.f32 "
                        "{%0,%1,%2,%3}, {%4,%5,%6,%7}, {%8,%9}, {%0,%1,%2,%3};"
                        : "+f"(c[0]), "+f"(c[1]), "+f"(c[2]), "+f"(c[3])
                        : "r"(af[mt][0]), "r"(af[mt][1]),
                          "r"(af[mt][2]), "r"(af[mt][3]),
                          "r"(bb[nt][0]), "r"(bb[nt][1]));
                }
            }
        }

        int pf = kb + 3;
        if (pf < nk) load_stage(pf & 3, pf);
        cpa_commit();
    }
    __syncthreads();   // protect smem before any next use

    // ---------------- epilogue ----------------
    const int r  = lane >> 2;
    const int c2 = (lane & 3) << 1;
    #pragma unroll
    for (int mt = 0; mt < MT; mt++) {
        int row0 = m0 + wm * WMr + mt * 16 + r;
        int row1 = row0 + 8;
        int lb0 = 0, lb1 = 0;
        if (MODE == 0) { lb0 = labels[row0]; lb1 = labels[row1]; }
        #pragma unroll
        for (int nt = 0; nt < NT; nt++) {
            int col0 = n0 + wn * WNr + nt * 8 + c2;
            float v00 = acc[mt][nt][0], v01 = acc[mt][nt][1];
            float v10 = acc[mt][nt][2], v11 = acc[mt][nt][3];
            if (MODE == 0) {
                v00 += d_gbias[lb0 * G4 + col0];
                v01 += d_gbias[lb0 * G4 + col0 + 1];
                v10 += d_gbias[lb1 * G4 + col0];
                v11 += d_gbias[lb1 * G4 + col0 + 1];
                // cols interleaved 4k+gate: even lane (i,f), odd lane (g,o)
                float p00 = __shfl_xor_sync(0xffffffffu, v00, 1);
                float p01 = __shfl_xor_sync(0xffffffffu, v01, 1);
                float p10 = __shfl_xor_sync(0xffffffffu, v10, 1);
                float p11 = __shfl_xor_sync(0xffffffffu, v11, 1);
                if ((lane & 1) == 0) {
                    int k = col0 >> 2;
                    float cs0 = d_cst[row0 * HID + k];
                    float cn0 = sigf(v01) * cs0 + sigf(v00) * tanhf_(p00);
                    d_cst[row0 * HID + k] = cn0;
                    Xw[row0 * KXP + k] = __float2half(sigf(p01) * tanhf_(cn0));
                    float cs1 = d_cst[row1 * HID + k];
                    float cn1 = sigf(v11) * cs1 + sigf(v10) * tanhf_(p10);
                    d_cst[row1 * HID + k] = cn1;
                    Xw[row1 * KXP + k] = __float2half(sigf(p11) * tanhf_(cn1));
                }
            } else if (MODE == 1) {
                float b0v = bias[col0], b1v = bias[col0 + 1];
                d_t1[(size_t)row0 * HID + col0    ] = __float2half(fmaxf(v00 + b0v, 0.f));
                d_t1[(size_t)row0 * HID + col0 + 1] = __float2half(fmaxf(v01 + b1v, 0.f));
                d_t1[(size_t)row1 * HID + col0    ] = __float2half(fmaxf(v10 + b0v, 0.f));
                d_t1[(size_t)row1 * HID + col0 + 1] = __float2half(fmaxf(v11 + b1v, 0.f));
            } else {
                #pragma unroll
                for (int e = 0; e < 2; e++) {
                    int col = col0 + e;
                    if (col < OUTD) {
                        float bv = bias[col];
                        float a0 = (e == 0 ? v00 : v01) + bv;
                        float a1 = (e == 0 ? v10 : v11) + bv;
                        outp[((size_t)row0 * SEQL + t) * OUTD + col] = a0;
                        outp[((size_t)row1 * SEQL + t) * OUTD + col] = a1;
                        Xw[row0 * KXP + HID + col] = __float2half(a0);
                        Xw[row1 * KXP + HID + col] = __float2half(a1);
                    }
                }
            }
        }
    }
}

// ------------------------- persistent kernel -------------------------------
__global__ void __launch_bounds__(256)
rnn_persist(const int* __restrict__ labels,
            const float* __restrict__ b_fc1, const float* __restrict__ b_fc2,
            float* __restrict__ out, unsigned nblocks) {
    extern __shared__ __align__(16) __half smem[];
    const uint32_t sa = (uint32_t)__cvta_generic_to_shared(smem);

    unsigned ep = 0;
    const unsigned bx = blockIdx.x;

    for (int t = 0; t < SEQL; t++) {
        __half* Xcur = d_Xbuf[t & 1];
        __half* Xnxt = d_Xbuf[(t & 1) ^ 1];

        // gates + fused cell: 4m x 32n = 128 tiles of 128x256
        for (unsigned tile = bx; tile < 128; tile += nblocks)
            gemm_tile<0, 128, 256>((tile >> 5) * 128, (tile & 31) * 256,
                                   Xcur, Xnxt, labels, nullptr, nullptr, 0, sa);
        grid_sync(nblocks, ep);

        // fc1 + relu: 8m x 16n = 128 tiles of 64x128
        for (unsigned tile = bx; tile < 128; tile += nblocks)
            gemm_tile<1, 64, 128>((tile >> 4) * 64, (tile & 15) * 128,
                                  Xnxt, nullptr, nullptr, b_fc1, nullptr, 0, sa);
        grid_sync(nblocks, ep);

        // fc2: 8m x 4n = 32 tiles of 64x64
        for (unsigned tile = bx; tile < 32; tile += nblocks)
            gemm_tile<2, 64, 64>((tile >> 2) * 64, (tile & 3) * 64,
                                 d_t1, Xnxt, nullptr, b_fc2, out, t, sa);
        grid_sync(nblocks, ep);
    }
}

// ------------------------- launch ------------------------------------------
extern "C" void kernel_launch(void* const* d_in, const int* in_sizes, int n_in,
                              void* d_out, int out_size) {
    const float* inputs = (const float*)d_in[0];
    const int*   labels = (const int*)  d_in[1];
    // d_in[2] = length (constant 240)
    const float* W_enc  = (const float*)d_in[3];
    const float* b_enc  = (const float*)d_in[4];
    const float* W_ih   = (const float*)d_in[5];
    const float* b_ih   = (const float*)d_in[6];
    const float* W_hh   = (const float*)d_in[7];
    const float* b_hh   = (const float*)d_in[8];
    const float* W_fc1  = (const float*)d_in[9];
    const float* b_fc1  = (const float*)d_in[10];
    const float* W_fc2  = (const float*)d_in[11];
    const float* b_fc2  = (const float*)d_in[12];
    const float* W_inh  = (const float*)d_in[13];
    const float* b_inh  = (const float*)d_in[14];
    const float* W_inc  = (const float*)d_in[15];
    const float* b_inc  = (const float*)d_in[16];
    float* out = (float*)d_out;

    cudaFuncSetAttribute(rnn_persist,
                         cudaFuncAttributeMaxDynamicSharedMemorySize, SMEM_TOTAL);

    int dev = 0, sms = 0, occ = 0;
    cudaGetDevice(&dev);
    cudaDeviceGetAttribute(&sms, cudaDevAttrMultiProcessorCount, dev);
    cudaOccupancyMaxActiveBlocksPerMultiprocessor(&occ, rnn_persist, 256, SMEM_TOTAL);
    if (occ < 1) occ = 1;
    unsigned nblocks = (unsigned)(sms * occ);

    setupA<<<(int)(((size_t)G4 * KXP + 255) / 256), 256>>>(W_hh, W_ih);
    setupB<<<SB_TOT, 256>>>(inputs, W_enc, b_enc, W_ih, b_ih, b_hh,
                            W_fc1, W_fc2, W_inh, b_inh, W_inc, b_inc);
    rnn_persist<<<nblocks, 256, SMEM_TOTAL>>>(labels, b_fc1, b_fc2, out, nblocks);
}